// round 1
// baseline (speedup 1.0000x reference)
#include <cuda_runtime.h>
#include <math.h>

// Problem dims
#define NFEAT 6
#define PAIRS 15
#define EMBED 256
#define TOKENS 16384            // B*S = 32*512
#define KCAT 512                // 2*EMBED
#define KFIN 3840               // PAIRS*EMBED

// GEMM tiling
#define BM 128
#define BN 128
#define BK 16
#define TM 8
#define TN 8
// threads = (BM/TM)*(BN/TN) = 256

// Intermediate H: [t, p*256+d] row-major, stride KFIN. 15*16384*256 floats (~252 MB)
__device__ float g_H[(size_t)PAIRS * TOKENS * EMBED];

__constant__ int c_pi[PAIRS] = {0,0,0,0,0,1,1,1,1,2,2,2,3,3,4};
__constant__ int c_pj[PAIRS] = {1,2,3,4,5,2,3,4,5,3,4,5,4,5,5};

struct Smem {
    float As[2][BK][BM + 4];
    float Bs[2][BK][BN];
};

// Accumulate C[BM,BN] += A[BM,K] * B[K,BN]; A row-major lda, B row-major ldb.
// All dims assumed divisible (M%128==0, N%128==0, K%16==0) -- true for this problem.
__device__ __forceinline__ void sgemm_block(
    const float* __restrict__ A, int lda,
    const float* __restrict__ B, int ldb,
    int K, Smem& s, float acc[TM][TN])
{
    const int tid = threadIdx.x;
    const int tx = tid & 15;
    const int ty = tid >> 4;

    // A tile loader: 128x16 = 512 float4, 2 per thread; store transposed As[k][row]
    const int a_row0 = tid >> 2;
    const int a_col0 = (tid & 3) * 4;
    const int a_row1 = a_row0 + 64;      // (tid+256)>>2
    // B tile loader: 16x128 = 512 float4, 2 per thread
    const int b_row0 = tid >> 5;
    const int b_col0 = (tid & 31) * 4;
    const int b_row1 = b_row0 + 8;

    const int ntiles = K / BK;

    // Preload tile 0
    float4 av0 = *(const float4*)&A[(size_t)a_row0 * lda + a_col0];
    float4 av1 = *(const float4*)&A[(size_t)a_row1 * lda + a_col0];
    float4 bv0 = *(const float4*)&B[(size_t)b_row0 * ldb + b_col0];
    float4 bv1 = *(const float4*)&B[(size_t)b_row1 * ldb + b_col0];
    s.As[0][a_col0 + 0][a_row0] = av0.x;
    s.As[0][a_col0 + 1][a_row0] = av0.y;
    s.As[0][a_col0 + 2][a_row0] = av0.z;
    s.As[0][a_col0 + 3][a_row0] = av0.w;
    s.As[0][a_col0 + 0][a_row1] = av1.x;
    s.As[0][a_col0 + 1][a_row1] = av1.y;
    s.As[0][a_col0 + 2][a_row1] = av1.z;
    s.As[0][a_col0 + 3][a_row1] = av1.w;
    *(float4*)&s.Bs[0][b_row0][b_col0] = bv0;
    *(float4*)&s.Bs[0][b_row1][b_col0] = bv1;
    __syncthreads();

    for (int kt = 0; kt < ntiles; kt++) {
        const int cur = kt & 1;
        const int nxt = cur ^ 1;
        float4 na0, na1, nb0, nb1;
        const bool has_next = (kt + 1 < ntiles);
        if (has_next) {
            const float* An = A + (size_t)(kt + 1) * BK;
            const float* Bn = B + (size_t)(kt + 1) * BK * ldb;
            na0 = *(const float4*)&An[(size_t)a_row0 * lda + a_col0];
            na1 = *(const float4*)&An[(size_t)a_row1 * lda + a_col0];
            nb0 = *(const float4*)&Bn[(size_t)b_row0 * ldb + b_col0];
            nb1 = *(const float4*)&Bn[(size_t)b_row1 * ldb + b_col0];
        }

        #pragma unroll
        for (int k = 0; k < BK; k++) {
            float ar[TM], br[TN];
            #pragma unroll
            for (int r = 0; r < TM; r++) ar[r] = s.As[cur][k][ty * TM + r];
            #pragma unroll
            for (int c = 0; c < TN; c++) br[c] = s.Bs[cur][k][tx * TN + c];
            #pragma unroll
            for (int r = 0; r < TM; r++)
                #pragma unroll
                for (int c = 0; c < TN; c++)
                    acc[r][c] = fmaf(ar[r], br[c], acc[r][c]);
        }

        if (has_next) {
            s.As[nxt][a_col0 + 0][a_row0] = na0.x;
            s.As[nxt][a_col0 + 1][a_row0] = na0.y;
            s.As[nxt][a_col0 + 2][a_row0] = na0.z;
            s.As[nxt][a_col0 + 3][a_row0] = na0.w;
            s.As[nxt][a_col0 + 0][a_row1] = na1.x;
            s.As[nxt][a_col0 + 1][a_row1] = na1.y;
            s.As[nxt][a_col0 + 2][a_row1] = na1.z;
            s.As[nxt][a_col0 + 3][a_row1] = na1.w;
            *(float4*)&s.Bs[nxt][b_row0][b_col0] = nb0;
            *(float4*)&s.Bs[nxt][b_row1][b_col0] = nb1;
        }
        __syncthreads();
    }
}

// Stage 1: per pair p, H[t, p*256+d] = tanh(concat(f_i[t],f_j[t]) @ W_pair[p] + b_pair[p]) * mask
__global__ __launch_bounds__(256) void pair_gemm_kernel(
    const float* __restrict__ features,
    const float* __restrict__ W_pair,
    const float* __restrict__ b_pair,
    const int* __restrict__ NAS)
{
    __shared__ Smem s;
    const int p = blockIdx.z;
    const int row0 = blockIdx.y * BM;
    const int col0 = blockIdx.x * BN;

    const int tid = threadIdx.x;
    const int tx = tid & 15;
    const int ty = tid >> 4;

    const int fi = c_pi[p];
    const int fj = c_pj[p];
    const int nas_i = (fi < 2) ? 1 : NAS[fi];
    const int nas_j = (fj < 2) ? 1 : NAS[fj];
    const int mask = nas_i * nas_j;

    float* Hbase = g_H + (size_t)p * EMBED + col0;   // column block within row of stride KFIN

    if (mask == 0) {
        // zero-fill our 128x128 tile of H
        const float4 z = make_float4(0.f, 0.f, 0.f, 0.f);
        #pragma unroll
        for (int r = 0; r < TM; r++) {
            const size_t t = (size_t)(row0 + ty * TM + r);
            float* dst = Hbase + t * KFIN + tx * TN;
            *(float4*)&dst[0] = z;
            *(float4*)&dst[4] = z;
        }
        return;
    }

    const float* Ai = features + (size_t)fi * TOKENS * EMBED + (size_t)row0 * EMBED;
    const float* Aj = features + (size_t)fj * TOKENS * EMBED + (size_t)row0 * EMBED;
    const float* B0 = W_pair + (size_t)p * KCAT * EMBED + col0;           // rows [0,256)
    const float* B1 = B0 + (size_t)EMBED * EMBED;                         // rows [256,512)

    float acc[TM][TN];
    #pragma unroll
    for (int r = 0; r < TM; r++)
        #pragma unroll
        for (int c = 0; c < TN; c++) acc[r][c] = 0.f;

    sgemm_block(Ai, EMBED, B0, EMBED, EMBED, s, acc);
    sgemm_block(Aj, EMBED, B1, EMBED, EMBED, s, acc);

    // epilogue: bias + tanh
    float bias[TN];
    #pragma unroll
    for (int c = 0; c < TN; c++) bias[c] = b_pair[p * EMBED + col0 + tx * TN + c];

    #pragma unroll
    for (int r = 0; r < TM; r++) {
        const size_t t = (size_t)(row0 + ty * TM + r);
        float* dst = Hbase + t * KFIN + tx * TN;
        float v[TN];
        #pragma unroll
        for (int c = 0; c < TN; c++) v[c] = tanhf(acc[r][c] + bias[c]);
        *(float4*)&dst[0] = make_float4(v[0], v[1], v[2], v[3]);
        *(float4*)&dst[4] = make_float4(v[4], v[5], v[6], v[7]);
    }
}

// Stage 2: out[t,d] = H[t,:] @ W_final + b_final
__global__ __launch_bounds__(256) void final_gemm_kernel(
    const float* __restrict__ W_final,
    const float* __restrict__ b_final,
    float* __restrict__ out)
{
    __shared__ Smem s;
    const int row0 = blockIdx.y * BM;
    const int col0 = blockIdx.x * BN;

    const int tid = threadIdx.x;
    const int tx = tid & 15;
    const int ty = tid >> 4;

    const float* A = g_H + (size_t)row0 * KFIN;
    const float* B = W_final + col0;

    float acc[TM][TN];
    #pragma unroll
    for (int r = 0; r < TM; r++)
        #pragma unroll
        for (int c = 0; c < TN; c++) acc[r][c] = 0.f;

    sgemm_block(A, KFIN, B, EMBED, KFIN, s, acc);

    float bias[TN];
    #pragma unroll
    for (int c = 0; c < TN; c++) bias[c] = b_final[col0 + tx * TN + c];

    #pragma unroll
    for (int r = 0; r < TM; r++) {
        const size_t t = (size_t)(row0 + ty * TM + r);
        float* dst = out + t * EMBED + col0 + tx * TN;
        float v[TN];
        #pragma unroll
        for (int c = 0; c < TN; c++) v[c] = acc[r][c] + bias[c];
        *(float4*)&dst[0] = make_float4(v[0], v[1], v[2], v[3]);
        *(float4*)&dst[4] = make_float4(v[4], v[5], v[6], v[7]);
    }
}

extern "C" void kernel_launch(void* const* d_in, const int* in_sizes, int n_in,
                              void* d_out, int out_size) {
    const float* features = (const float*)d_in[0];
    const float* W_pair   = (const float*)d_in[1];
    const float* b_pair   = (const float*)d_in[2];
    const float* W_final  = (const float*)d_in[3];
    const float* b_final  = (const float*)d_in[4];
    const int*   NAS      = (const int*)d_in[5];
    float* out = (float*)d_out;

    dim3 block(256);
    dim3 grid1(EMBED / BN, TOKENS / BM, PAIRS);   // (2, 128, 15)
    pair_gemm_kernel<<<grid1, block>>>(features, W_pair, b_pair, NAS);

    dim3 grid2(EMBED / BN, TOKENS / BM);          // (2, 128)
    final_gemm_kernel<<<grid2, block>>>(W_final, b_final, out);
}

// round 4
// speedup vs baseline: 5.9774x; 5.9774x over previous
#include <cuda_runtime.h>
#include <math.h>

// Problem dims
#define NFEAT 6
#define PAIRS 15
#define EMBED 256
#define TOKENS 16384            // B*S = 32*512
#define KCAT 512                // 2*EMBED
#define KFIN 3840               // PAIRS*EMBED

// GEMM tiling
#define BM 128
#define BN 128
#define BK 16
#define TM 8
#define TN 8
// threads = (BM/TM)*(BN/TN) = 256

// Intermediate H: [t, p*256+d] row-major, stride KFIN.
// Masked pairs' chunks are NEVER written and NEVER read (stage 2 skips them).
__device__ float g_H[(size_t)PAIRS * TOKENS * EMBED];

__constant__ int c_pi[PAIRS] = {0,0,0,0,0,1,1,1,1,2,2,2,3,3,4};
__constant__ int c_pj[PAIRS] = {1,2,3,4,5,2,3,4,5,3,4,5,4,5,5};

struct Smem {
    float As[2][BK][BM + 4];
    float Bs[2][BK][BN];
};

// Accumulate C[BM,BN] += A[BM,K] * B[K,BN]; A row-major lda, B row-major ldb.
// Dims assumed divisible (M%128==0, N%128==0, K%16==0) -- true here.
__device__ __forceinline__ void sgemm_block(
    const float* __restrict__ A, int lda,
    const float* __restrict__ B, int ldb,
    int K, Smem& s, float acc[TM][TN])
{
    const int tid = threadIdx.x;
    const int tx = tid & 15;
    const int ty = tid >> 4;

    // A tile loader: 128x16 = 512 float4, 2 per thread; store transposed As[k][row]
    const int a_row0 = tid >> 2;
    const int a_col0 = (tid & 3) * 4;
    const int a_row1 = a_row0 + 64;
    // B tile loader: 16x128 = 512 float4, 2 per thread
    const int b_row0 = tid >> 5;
    const int b_col0 = (tid & 31) * 4;
    const int b_row1 = b_row0 + 8;

    const int ntiles = K / BK;

    // Preload tile 0
    float4 av0 = *(const float4*)&A[(size_t)a_row0 * lda + a_col0];
    float4 av1 = *(const float4*)&A[(size_t)a_row1 * lda + a_col0];
    float4 bv0 = *(const float4*)&B[(size_t)b_row0 * ldb + b_col0];
    float4 bv1 = *(const float4*)&B[(size_t)b_row1 * ldb + b_col0];
    s.As[0][a_col0 + 0][a_row0] = av0.x;
    s.As[0][a_col0 + 1][a_row0] = av0.y;
    s.As[0][a_col0 + 2][a_row0] = av0.z;
    s.As[0][a_col0 + 3][a_row0] = av0.w;
    s.As[0][a_col0 + 0][a_row1] = av1.x;
    s.As[0][a_col0 + 1][a_row1] = av1.y;
    s.As[0][a_col0 + 2][a_row1] = av1.z;
    s.As[0][a_col0 + 3][a_row1] = av1.w;
    *(float4*)&s.Bs[0][b_row0][b_col0] = bv0;
    *(float4*)&s.Bs[0][b_row1][b_col0] = bv1;
    __syncthreads();

    for (int kt = 0; kt < ntiles; kt++) {
        const int cur = kt & 1;
        const int nxt = cur ^ 1;
        float4 na0, na1, nb0, nb1;
        const bool has_next = (kt + 1 < ntiles);
        if (has_next) {
            const float* An = A + (size_t)(kt + 1) * BK;
            const float* Bn = B + (size_t)(kt + 1) * BK * ldb;
            na0 = *(const float4*)&An[(size_t)a_row0 * lda + a_col0];
            na1 = *(const float4*)&An[(size_t)a_row1 * lda + a_col0];
            nb0 = *(const float4*)&Bn[(size_t)b_row0 * ldb + b_col0];
            nb1 = *(const float4*)&Bn[(size_t)b_row1 * ldb + b_col0];
        }

        #pragma unroll
        for (int k = 0; k < BK; k++) {
            float ar[TM], br[TN];
            #pragma unroll
            for (int r = 0; r < TM; r++) ar[r] = s.As[cur][k][ty * TM + r];
            #pragma unroll
            for (int c = 0; c < TN; c++) br[c] = s.Bs[cur][k][tx * TN + c];
            #pragma unroll
            for (int r = 0; r < TM; r++)
                #pragma unroll
                for (int c = 0; c < TN; c++)
                    acc[r][c] = fmaf(ar[r], br[c], acc[r][c]);
        }

        if (has_next) {
            s.As[nxt][a_col0 + 0][a_row0] = na0.x;
            s.As[nxt][a_col0 + 1][a_row0] = na0.y;
            s.As[nxt][a_col0 + 2][a_row0] = na0.z;
            s.As[nxt][a_col0 + 3][a_row0] = na0.w;
            s.As[nxt][a_col0 + 0][a_row1] = na1.x;
            s.As[nxt][a_col0 + 1][a_row1] = na1.y;
            s.As[nxt][a_col0 + 2][a_row1] = na1.z;
            s.As[nxt][a_col0 + 3][a_row1] = na1.w;
            *(float4*)&s.Bs[nxt][b_row0][b_col0] = nb0;
            *(float4*)&s.Bs[nxt][b_row1][b_col0] = nb1;
        }
        __syncthreads();
    }
}

__device__ __forceinline__ int pair_active(int p, const int* __restrict__ NAS) {
    const int fi = c_pi[p];
    const int fj = c_pj[p];
    const int ni = (fi < 2) ? 1 : NAS[fi];
    const int nj = (fj < 2) ? 1 : NAS[fj];
    return ni * nj;
}

// Stage 1: per ACTIVE pair p, H[t, p*256+d] = tanh(concat(f_i,f_j)[t] @ W_pair[p] + b_pair[p]).
// Masked pairs: exit immediately (their H is never read).
__global__ __launch_bounds__(256) void pair_gemm_kernel(
    const float* __restrict__ features,
    const float* __restrict__ W_pair,
    const float* __restrict__ b_pair,
    const int* __restrict__ NAS)
{
    __shared__ Smem s;
    const int p = blockIdx.z;
    if (!pair_active(p, NAS)) return;

    const int row0 = blockIdx.y * BM;
    const int col0 = blockIdx.x * BN;

    const int tid = threadIdx.x;
    const int tx = tid & 15;
    const int ty = tid >> 4;

    const int fi = c_pi[p];
    const int fj = c_pj[p];

    const float* Ai = features + (size_t)fi * TOKENS * EMBED + (size_t)row0 * EMBED;
    const float* Aj = features + (size_t)fj * TOKENS * EMBED + (size_t)row0 * EMBED;
    const float* B0 = W_pair + (size_t)p * KCAT * EMBED + col0;           // rows [0,256)
    const float* B1 = B0 + (size_t)EMBED * EMBED;                         // rows [256,512)

    float acc[TM][TN];
    #pragma unroll
    for (int r = 0; r < TM; r++)
        #pragma unroll
        for (int c = 0; c < TN; c++) acc[r][c] = 0.f;

    sgemm_block(Ai, EMBED, B0, EMBED, EMBED, s, acc);
    sgemm_block(Aj, EMBED, B1, EMBED, EMBED, s, acc);

    // epilogue: bias + tanh
    float bias[TN];
    #pragma unroll
    for (int c = 0; c < TN; c++) bias[c] = b_pair[p * EMBED + col0 + tx * TN + c];

    float* Hbase = g_H + (size_t)p * EMBED + col0;
    #pragma unroll
    for (int r = 0; r < TM; r++) {
        const size_t t = (size_t)(row0 + ty * TM + r);
        float* dst = Hbase + t * KFIN + tx * TN;
        float v[TN];
        #pragma unroll
        for (int c = 0; c < TN; c++) v[c] = tanhf(acc[r][c] + bias[c]);
        *(float4*)&dst[0] = make_float4(v[0], v[1], v[2], v[3]);
        *(float4*)&dst[4] = make_float4(v[4], v[5], v[6], v[7]);
    }
}

// Stage 2: out[t,d] = sum over ACTIVE pairs of H_p[t,:] @ W_final[p*256:(p+1)*256, :] + b_final.
// Masked pairs' K-chunks contribute exactly zero -> skipped entirely.
__global__ __launch_bounds__(256) void final_gemm_kernel(
    const float* __restrict__ W_final,
    const float* __restrict__ b_final,
    const int* __restrict__ NAS,
    float* __restrict__ out)
{
    __shared__ Smem s;
    const int row0 = blockIdx.y * BM;
    const int col0 = blockIdx.x * BN;

    const int tid = threadIdx.x;
    const int tx = tid & 15;
    const int ty = tid >> 4;

    float acc[TM][TN];
    #pragma unroll
    for (int r = 0; r < TM; r++)
        #pragma unroll
        for (int c = 0; c < TN; c++) acc[r][c] = 0.f;

    #pragma unroll 1
    for (int p = 0; p < PAIRS; p++) {
        if (!pair_active(p, NAS)) continue;
        const float* A = g_H + (size_t)row0 * KFIN + (size_t)p * EMBED;
        const float* B = W_final + (size_t)p * EMBED * EMBED + col0;
        sgemm_block(A, KFIN, B, EMBED, EMBED, s, acc);
    }

    float bias[TN];
    #pragma unroll
    for (int c = 0; c < TN; c++) bias[c] = b_final[col0 + tx * TN + c];

    #pragma unroll
    for (int r = 0; r < TM; r++) {
        const size_t t = (size_t)(row0 + ty * TM + r);
        float* dst = out + t * EMBED + col0 + tx * TN;
        float v[TN];
        #pragma unroll
        for (int c = 0; c < TN; c++) v[c] = acc[r][c] + bias[c];
        *(float4*)&dst[0] = make_float4(v[0], v[1], v[2], v[3]);
        *(float4*)&dst[4] = make_float4(v[4], v[5], v[6], v[7]);
    }
}

extern "C" void kernel_launch(void* const* d_in, const int* in_sizes, int n_in,
                              void* d_out, int out_size) {
    const float* features = (const float*)d_in[0];
    const float* W_pair   = (const float*)d_in[1];
    const float* b_pair   = (const float*)d_in[2];
    const float* W_final  = (const float*)d_in[3];
    const float* b_final  = (const float*)d_in[4];
    const int*   NAS      = (const int*)d_in[5];
    float* out = (float*)d_out;

    dim3 block(256);
    dim3 grid1(EMBED / BN, TOKENS / BM, PAIRS);   // (2, 128, 15); masked blocks exit fast
    pair_gemm_kernel<<<grid1, block>>>(features, W_pair, b_pair, NAS);

    dim3 grid2(EMBED / BN, TOKENS / BM);          // (2, 128)
    final_gemm_kernel<<<grid2, block>>>(W_final, b_final, NAS, out);
}

// round 5
// speedup vs baseline: 11.5871x; 1.9385x over previous
#include <cuda_runtime.h>
#include <stdint.h>
#include <math.h>

// ---------------- problem dims ----------------
#define NFEAT  6
#define PAIRS  15
#define EMBED  256
#define TOKENS 16384          // B*S
#define KCAT   512            // 2*EMBED
#define KFIN   3840           // PAIRS*EMBED

// ---------------- CTA tiling ----------------
#define BM 128
#define BN 128
#define BK 16
// 8 warps (256 thr): warp grid 2x4 -> warp tile 64x32
// per warp: 4 m16 tiles x 4 n8 tiles of m16n8k8 tf32 mma

// ---------------- scratch (static device globals) ----------------
__device__ float g_H[(size_t)PAIRS * TOKENS * EMBED];   // [t][p*256+d], stride KFIN (tf32-rounded)
__device__ float g_Wp[(size_t)PAIRS * KCAT * EMBED];    // tf32-rounded W_pair
__device__ float g_Wf[(size_t)KFIN * EMBED];            // tf32-rounded W_final

__constant__ int c_pi[PAIRS] = {0,0,0,0,0,1,1,1,1,2,2,2,3,3,4};
__constant__ int c_pj[PAIRS] = {1,2,3,4,5,2,3,4,5,3,4,5,4,5,5};

// ---------------- helpers ----------------
__device__ __forceinline__ uint32_t f2tf(float x) {
    uint32_t u; asm("cvt.rn.tf32.f32 %0, %1;" : "=r"(u) : "f"(x)); return u;
}
__device__ __forceinline__ float f2tf_f(float x) { return __uint_as_float(f2tf(x)); }

// accurate fast tanh: (1-e)/(1+e), e = 2^(-2x*log2e); err ~1e-6
__device__ __forceinline__ float fast_tanh(float x) {
    float ax = fabsf(x);
    float e; asm("ex2.approx.f32 %0, %1;" : "=f"(e) : "f"(-2.8853900817779268f * ax));
    float d; asm("rcp.approx.f32 %0, %1;" : "=f"(d) : "f"(1.0f + e));
    float t = (1.0f - e) * d;
    return copysignf(t, x);
}

__device__ __forceinline__ void mma_tf32(float* c, const uint32_t* a, const uint32_t* b) {
    asm volatile(
        "mma.sync.aligned.m16n8k8.row.col.f32.tf32.tf32.f32 "
        "{%0,%1,%2,%3}, {%4,%5,%6,%7}, {%8,%9}, {%0,%1,%2,%3};\n"
        : "+f"(c[0]), "+f"(c[1]), "+f"(c[2]), "+f"(c[3])
        : "r"(a[0]), "r"(a[1]), "r"(a[2]), "r"(a[3]), "r"(b[0]), "r"(b[1]));
}

__device__ __forceinline__ int pair_active(int p, const int* __restrict__ NAS) {
    const int fi = c_pi[p], fj = c_pj[p];
    return ((fi < 2) ? 1 : NAS[fi]) * ((fj < 2) ? 1 : NAS[fj]);
}

// ---------------- smem ----------------
#define ASTRIDE 136
#define BUFSZ  (16 * ASTRIDE)   // u32 per buffer
struct MSmem { uint32_t As[2][BUFSZ]; uint32_t Bs[2][BUFSZ]; };  // 34816 B

// Accumulate C[128,128] += A[128,256] (row-major, lda) * B[256,128] (row-major [k][n], ldb).
// K fixed = 256 (16 tiles of BK=16). CVT: round A elements to tf32 on load.
template<bool CVT>
__device__ __forceinline__ void mma_block(
    const float* __restrict__ A, int lda,
    const float* __restrict__ B, int ldb,
    MSmem& s, float acc[4][4][4])
{
    const int tid  = threadIdx.x;
    const int lane = tid & 31;
    const int wid  = tid >> 5;
    const int g    = lane >> 2;      // 0..7
    const int tig  = lane & 3;       // 0..3
    const int wm   = (wid >> 2) * 64;
    const int wn   = (wid & 3) * 32;

    // A loader: 128x16 floats, 2 float4/thread; store transposed+swizzled As[k][m']
    const int a_row0 = tid >> 2;           // 0..63
    const int a_row1 = a_row0 + 64;
    const int ac     = (tid & 3) * 4;      // k base (0,4,8,12)
    // B loader: 16x128 floats, 2 uint4/thread; plain Bs[k][n]
    const int b_row0 = tid >> 5;           // 0..7
    const int b_row1 = b_row0 + 8;
    const int bc     = (tid & 31) * 4;

    const int NT = 256 / BK;               // 16

    float4 av0 = *(const float4*)&A[(size_t)a_row0 * lda + ac];
    float4 av1 = *(const float4*)&A[(size_t)a_row1 * lda + ac];
    uint4  bv0 = *(const uint4*)&B[(size_t)b_row0 * ldb + bc];
    uint4  bv1 = *(const uint4*)&B[(size_t)b_row1 * ldb + bc];

    // A swizzle: col' = (m + 2*(k&12)) & 127 -> conflict-free STS and LDS
    const int asw = ac << 1;   // 2*(k&12) with k = ac+i (i<4)
#define STORE_A(buf, v, m) do { \
        uint32_t w0 = CVT ? f2tf((v).x) : __float_as_uint((v).x); \
        uint32_t w1 = CVT ? f2tf((v).y) : __float_as_uint((v).y); \
        uint32_t w2 = CVT ? f2tf((v).z) : __float_as_uint((v).z); \
        uint32_t w3 = CVT ? f2tf((v).w) : __float_as_uint((v).w); \
        int mm = ((m) + asw) & 127; \
        s.As[buf][(ac + 0) * ASTRIDE + mm] = w0; \
        s.As[buf][(ac + 1) * ASTRIDE + mm] = w1; \
        s.As[buf][(ac + 2) * ASTRIDE + mm] = w2; \
        s.As[buf][(ac + 3) * ASTRIDE + mm] = w3; \
    } while (0)
#define STORE_B(buf, v, kr) \
        *(uint4*)&s.Bs[buf][(kr) * ASTRIDE + bc] = (v)

    STORE_A(0, av0, a_row0); STORE_A(0, av1, a_row1);
    STORE_B(0, bv0, b_row0); STORE_B(0, bv1, b_row1);
    __syncthreads();

    for (int kt = 0; kt < NT; kt++) {
        const int cur = kt & 1, nxt = cur ^ 1;
        const bool hn = (kt + 1 < NT);
        if (hn) {
            const float* An = A + (kt + 1) * BK;
            const float* Bn = B + (size_t)(kt + 1) * BK * ldb;
            av0 = *(const float4*)&An[(size_t)a_row0 * lda + ac];
            av1 = *(const float4*)&An[(size_t)a_row1 * lda + ac];
            bv0 = *(const uint4*)&Bn[(size_t)b_row0 * ldb + bc];
            bv1 = *(const uint4*)&Bn[(size_t)b_row1 * ldb + bc];
        }

        #pragma unroll
        for (int ks8 = 0; ks8 < 2; ks8++) {
            const int ks = ks8 * 8;
            const uint32_t* Ak0 = &s.As[cur][(ks + tig) * ASTRIDE];
            const uint32_t* Ak4 = &s.As[cur][(ks + tig + 4) * ASTRIDE];
            const int o0 = ks << 1;            // swizzle offset for k in [ks, ks+4)
            const int o4 = (ks << 1) + 8;      // for k in [ks+4, ks+8)
            uint32_t a[4][4];
            #pragma unroll
            for (int mi = 0; mi < 4; mi++) {
                const int m = wm + mi * 16 + g;
                a[mi][0] = Ak0[(m + o0) & 127];
                a[mi][1] = Ak0[(m + 8 + o0) & 127];
                a[mi][2] = Ak4[(m + o4) & 127];
                a[mi][3] = Ak4[(m + 8 + o4) & 127];
            }
            const uint32_t* Bk0 = &s.Bs[cur][(ks + tig) * ASTRIDE + wn + g];
            const uint32_t* Bk4 = &s.Bs[cur][(ks + tig + 4) * ASTRIDE + wn + g];
            uint32_t b[4][2];
            #pragma unroll
            for (int ni = 0; ni < 4; ni++) { b[ni][0] = Bk0[ni * 8]; b[ni][1] = Bk4[ni * 8]; }
            #pragma unroll
            for (int mi = 0; mi < 4; mi++)
                #pragma unroll
                for (int ni = 0; ni < 4; ni++)
                    mma_tf32(acc[mi][ni], a[mi], b[ni]);
        }

        if (hn) {
            STORE_A(nxt, av0, a_row0); STORE_A(nxt, av1, a_row1);
            STORE_B(nxt, bv0, b_row0); STORE_B(nxt, bv1, b_row1);
        }
        __syncthreads();
    }
#undef STORE_A
#undef STORE_B
}

// ---------------- prep: round weights to tf32 ----------------
__global__ void round_w_kernel(const float* __restrict__ Wp, const float* __restrict__ Wf) {
    const size_t n1 = (size_t)PAIRS * KCAT * EMBED / 4;
    const size_t n2 = (size_t)KFIN * EMBED / 4;
    for (size_t i = (size_t)blockIdx.x * blockDim.x + threadIdx.x; i < n1 + n2;
         i += (size_t)gridDim.x * blockDim.x) {
        float4 v;
        if (i < n1) v = ((const float4*)Wp)[i];
        else        v = ((const float4*)Wf)[i - n1];
        v.x = f2tf_f(v.x); v.y = f2tf_f(v.y); v.z = f2tf_f(v.z); v.w = f2tf_f(v.w);
        if (i < n1) ((float4*)g_Wp)[i] = v;
        else        ((float4*)g_Wf)[i - n1] = v;
    }
}

// ---------------- stage 1 ----------------
__global__ __launch_bounds__(256) void pair_gemm_kernel(
    const float* __restrict__ features,
    const float* __restrict__ b_pair,
    const int* __restrict__ NAS)
{
    __shared__ MSmem s;
    const int p = blockIdx.z;
    if (!pair_active(p, NAS)) return;

    const int row0 = blockIdx.y * BM;
    const int col0 = blockIdx.x * BN;
    const int fi = c_pi[p], fj = c_pj[p];

    float acc[4][4][4];
    #pragma unroll
    for (int mi = 0; mi < 4; mi++)
        #pragma unroll
        for (int ni = 0; ni < 4; ni++)
            #pragma unroll
            for (int r = 0; r < 4; r++) acc[mi][ni][r] = 0.f;

    const float* Ai = features + ((size_t)fi * TOKENS + row0) * EMBED;
    const float* Aj = features + ((size_t)fj * TOKENS + row0) * EMBED;
    const float* B0 = g_Wp + (size_t)p * KCAT * EMBED + col0;
    const float* B1 = B0 + (size_t)EMBED * EMBED;

    mma_block<true>(Ai, EMBED, B0, EMBED, s, acc);
    mma_block<true>(Aj, EMBED, B1, EMBED, s, acc);

    // epilogue: bias + tanh + tf32 round -> g_H
    const int lane = threadIdx.x & 31, wid = threadIdx.x >> 5;
    const int g = lane >> 2, tig = lane & 3;
    const int wm = (wid >> 2) * 64, wn = (wid & 3) * 32;

    #pragma unroll
    for (int ni = 0; ni < 4; ni++) {
        const int c = col0 + wn + ni * 8 + tig * 2;
        const float2 bb = *(const float2*)&b_pair[p * EMBED + c];
        #pragma unroll
        for (int mi = 0; mi < 4; mi++) {
            const int r0 = row0 + wm + mi * 16 + g;
            const int r1 = r0 + 8;
            float* d0 = &g_H[(size_t)r0 * KFIN + p * EMBED + c];
            float* d1 = &g_H[(size_t)r1 * KFIN + p * EMBED + c];
            float2 v0, v1;
            v0.x = f2tf_f(fast_tanh(acc[mi][ni][0] + bb.x));
            v0.y = f2tf_f(fast_tanh(acc[mi][ni][1] + bb.y));
            v1.x = f2tf_f(fast_tanh(acc[mi][ni][2] + bb.x));
            v1.y = f2tf_f(fast_tanh(acc[mi][ni][3] + bb.y));
            *(float2*)d0 = v0;
            *(float2*)d1 = v1;
        }
    }
}

// ---------------- stage 2 ----------------
__global__ __launch_bounds__(256) void final_gemm_kernel(
    const float* __restrict__ b_final,
    const int* __restrict__ NAS,
    float* __restrict__ out)
{
    __shared__ MSmem s;
    const int row0 = blockIdx.y * BM;
    const int col0 = blockIdx.x * BN;

    float acc[4][4][4];
    #pragma unroll
    for (int mi = 0; mi < 4; mi++)
        #pragma unroll
        for (int ni = 0; ni < 4; ni++)
            #pragma unroll
            for (int r = 0; r < 4; r++) acc[mi][ni][r] = 0.f;

    #pragma unroll 1
    for (int p = 0; p < PAIRS; p++) {
        if (!pair_active(p, NAS)) continue;
        const float* A = g_H + (size_t)row0 * KFIN + (size_t)p * EMBED;
        const float* B = g_Wf + ((size_t)p * EMBED) * EMBED + col0;
        mma_block<false>(A, KFIN, B, EMBED, s, acc);
    }

    const int lane = threadIdx.x & 31, wid = threadIdx.x >> 5;
    const int g = lane >> 2, tig = lane & 3;
    const int wm = (wid >> 2) * 64, wn = (wid & 3) * 32;

    #pragma unroll
    for (int ni = 0; ni < 4; ni++) {
        const int c = col0 + wn + ni * 8 + tig * 2;
        const float2 bb = *(const float2*)&b_final[c];
        #pragma unroll
        for (int mi = 0; mi < 4; mi++) {
            const int r0 = row0 + wm + mi * 16 + g;
            const int r1 = r0 + 8;
            float2 v0 = make_float2(acc[mi][ni][0] + bb.x, acc[mi][ni][1] + bb.y);
            float2 v1 = make_float2(acc[mi][ni][2] + bb.x, acc[mi][ni][3] + bb.y);
            *(float2*)&out[(size_t)r0 * EMBED + c] = v0;
            *(float2*)&out[(size_t)r1 * EMBED + c] = v1;
        }
    }
}

// ---------------- launch ----------------
extern "C" void kernel_launch(void* const* d_in, const int* in_sizes, int n_in,
                              void* d_out, int out_size) {
    const float* features = (const float*)d_in[0];
    const float* W_pair   = (const float*)d_in[1];
    const float* b_pair   = (const float*)d_in[2];
    const float* W_final  = (const float*)d_in[3];
    const float* b_final  = (const float*)d_in[4];
    const int*   NAS      = (const int*)d_in[5];
    float* out = (float*)d_out;

    round_w_kernel<<<1024, 256>>>(W_pair, W_final);

    dim3 block(256);
    dim3 grid1(EMBED / BN, TOKENS / BM, PAIRS);   // (2, 128, 15); masked blocks exit fast
    pair_gemm_kernel<<<grid1, block>>>(features, b_pair, NAS);

    dim3 grid2(EMBED / BN, TOKENS / BM);          // (2, 128)
    final_gemm_kernel<<<grid2, block>>>(b_final, NAS, out);
}

// round 6
// speedup vs baseline: 13.7344x; 1.1853x over previous
#include <cuda_runtime.h>
#include <stdint.h>
#include <math.h>

// ---------------- problem dims ----------------
#define NFEAT  6
#define PAIRS  15
#define EMBED  256
#define TOKENS 16384          // B*S
#define KCAT   512            // 2*EMBED

// ---------------- CTA tiling ----------------
// grid = TOKENS/64 = 256 CTAs, 256 threads (8 warps), warp grid 1x8
// warp tile 64(m) x 32(n): 4 m16-tiles x 4 n8-tiles of m16n8k8 tf32 mma
#define BM 64
#define BN 256
#define BK 16

// ---------------- smem layout (u32 units) ----------------
#define ASTR 72               // stride of A/H k-rows (64 cols + pad); 72 % 32 == 8
#define BSTR 264              // stride of B k-rows (256 cols + pad); 264 % 32 == 8
#define AS_BUF (16 * ASTR)    // 1152 u32 per A buffer
#define BS_BUF (16 * BSTR)    // 4224 u32 per B buffer
#define OFF_AS 0
#define OFF_BS (2 * AS_BUF)                 // 2304
#define OFF_HS (OFF_BS + 2 * BS_BUF)        // 10752
#define SMEM_U32 (OFF_HS + 256 * ASTR)      // 10752 + 18432 = 29184
#define SMEM_BYTES (SMEM_U32 * 4)           // 116736 B

__constant__ int c_pi[PAIRS] = {0,0,0,0,0,1,1,1,1,2,2,2,3,3,4};
__constant__ int c_pj[PAIRS] = {1,2,3,4,5,2,3,4,5,3,4,5,4,5,5};

// ---------------- helpers ----------------
__device__ __forceinline__ uint32_t f2tf(float x) {
    uint32_t u; asm("cvt.rn.tf32.f32 %0, %1;" : "=r"(u) : "f"(x)); return u;
}
// accurate fast tanh: (1-e)/(1+e), e = 2^(-2x*log2e); err ~1e-6
__device__ __forceinline__ float fast_tanh(float x) {
    float ax = fabsf(x);
    float e; asm("ex2.approx.f32 %0, %1;" : "=f"(e) : "f"(-2.8853900817779268f * ax));
    float d; asm("rcp.approx.f32 %0, %1;" : "=f"(d) : "f"(1.0f + e));
    float t = (1.0f - e) * d;
    return copysignf(t, x);
}
__device__ __forceinline__ void mma_tf32(float* c, const uint32_t* a, const uint32_t* b) {
    asm volatile(
        "mma.sync.aligned.m16n8k8.row.col.f32.tf32.tf32.f32 "
        "{%0,%1,%2,%3}, {%4,%5,%6,%7}, {%8,%9}, {%0,%1,%2,%3};\n"
        : "+f"(c[0]), "+f"(c[1]), "+f"(c[2]), "+f"(c[3])
        : "r"(a[0]), "r"(a[1]), "r"(a[2]), "r"(a[3]), "r"(b[0]), "r"(b[1]));
}
__device__ __forceinline__ int pair_active(int p, const int* __restrict__ NAS) {
    const int fi = c_pi[p], fj = c_pj[p];
    return ((fi < 2) ? 1 : NAS[fi]) * ((fj < 2) ? 1 : NAS[fj]);
}

// compute 16 k-steps (one BK tile) of mma into acc; A-operand rows at strideASTR
// bufA points at k-row 0 of the tile; bufB likewise.
__device__ __forceinline__ void tile_mma(const uint32_t* __restrict__ bufA,
                                         const uint32_t* __restrict__ bufB,
                                         int tig, int g, int wn,
                                         float acc[4][4][4]) {
    #pragma unroll
    for (int ks8 = 0; ks8 < 2; ks8++) {
        const int ks = ks8 * 8;
        const uint32_t* Ak0 = bufA + (ks + tig) * ASTR;
        const uint32_t* Ak4 = bufA + (ks + tig + 4) * ASTR;
        const int o0 = ks << 1;
        const int o4 = (ks << 1) + 8;
        uint32_t a[4][4];
        #pragma unroll
        for (int mi = 0; mi < 4; mi++) {
            const int m = mi * 16 + g;
            a[mi][0] = Ak0[(m + o0) & 63];
            a[mi][1] = Ak0[(m + 8 + o0) & 63];
            a[mi][2] = Ak4[(m + o4) & 63];
            a[mi][3] = Ak4[(m + 8 + o4) & 63];
        }
        const uint32_t* Bk0 = bufB + (ks + tig) * BSTR + wn + g;
        const uint32_t* Bk4 = bufB + (ks + tig + 4) * BSTR + wn + g;
        uint32_t b[4][2];
        #pragma unroll
        for (int ni = 0; ni < 4; ni++) { b[ni][0] = Bk0[ni * 8]; b[ni][1] = Bk4[ni * 8]; }
        #pragma unroll
        for (int mi = 0; mi < 4; mi++)
            #pragma unroll
            for (int ni = 0; ni < 4; ni++)
                mma_tf32(acc[mi][ni], a[mi], b[ni]);
    }
}

// ---------------- fused kernel ----------------
__global__ __launch_bounds__(256, 1) void fused_kernel(
    const float* __restrict__ features,
    const float* __restrict__ W_pair,
    const float* __restrict__ b_pair,
    const float* __restrict__ W_final,
    const float* __restrict__ b_final,
    const int* __restrict__ NAS,
    float* __restrict__ out)
{
    extern __shared__ uint32_t sm[];
    uint32_t* const smA = sm + OFF_AS;
    uint32_t* const smB = sm + OFF_BS;
    uint32_t* const Hs  = sm + OFF_HS;

    const int tid = threadIdx.x;
    const int lane = tid & 31, wid = tid >> 5;
    const int g = lane >> 2, tig = lane & 3;
    const int wn = wid * 32;
    const int row0 = blockIdx.x * BM;

    // A loader: 64x16 tile, 1 float4/thread; swizzled transposed store As[k][m']
    const int a_row = tid >> 2;           // 0..63
    const int a_kb  = (tid & 3) * 4;      // 0,4,8,12
    const int a_col = (a_row + 2 * a_kb) & 63;
    // B loader: 16x256 tile, 4 uint4/thread (rows b_r0+4q), plain Bs[k][n]
    const int b_r0 = tid >> 6;            // 0..3
    const int b_c0 = (tid & 63) * 4;

#define STORE_A(bufp, v) do { \
        uint32_t* d_ = (bufp) + a_kb * ASTR + a_col; \
        d_[0 * ASTR] = f2tf((v).x); d_[1 * ASTR] = f2tf((v).y); \
        d_[2 * ASTR] = f2tf((v).z); d_[3 * ASTR] = f2tf((v).w); \
    } while (0)
#define PREF_B(basep) do { \
        _Pragma("unroll") \
        for (int q_ = 0; q_ < 4; q_++) \
            bv[q_] = *(const float4*)&(basep)[(size_t)(b_r0 + 4 * q_) * EMBED + b_c0]; \
    } while (0)
#define STORE_B(bufp) do { \
        _Pragma("unroll") \
        for (int q_ = 0; q_ < 4; q_++) { \
            uint4 w_; \
            w_.x = f2tf(bv[q_].x); w_.y = f2tf(bv[q_].y); \
            w_.z = f2tf(bv[q_].z); w_.w = f2tf(bv[q_].w); \
            *(uint4*)&(bufp)[(b_r0 + 4 * q_) * BSTR + b_c0] = w_; \
        } \
    } while (0)

    float oacc[4][4][4];
    #pragma unroll
    for (int mi = 0; mi < 4; mi++)
        #pragma unroll
        for (int ni = 0; ni < 4; ni++)
            #pragma unroll
            for (int r = 0; r < 4; r++) oacc[mi][ni][r] = 0.f;

    #pragma unroll 1
    for (int p = 0; p < PAIRS; p++) {
        if (!pair_active(p, NAS)) continue;
        const int fi = c_pi[p], fj = c_pj[p];
        const float* Ai = features + ((size_t)fi * TOKENS + row0) * EMBED;
        const float* Aj = features + ((size_t)fj * TOKENS + row0) * EMBED;
        const float* Bp = W_pair + (size_t)p * KCAT * EMBED;

        float hacc[4][4][4];
        #pragma unroll
        for (int mi = 0; mi < 4; mi++)
            #pragma unroll
            for (int ni = 0; ni < 4; ni++)
                #pragma unroll
                for (int r = 0; r < 4; r++) hacc[mi][ni][r] = 0.f;

        // ---- stage 1: hacc = concat(fi,fj) @ Wp  (32 k-tiles of 16) ----
        float4 av = *(const float4*)&Ai[(size_t)a_row * EMBED + a_kb];
        float4 bv[4];
        PREF_B(Bp);
        STORE_A(smA, av);
        STORE_B(smB);
        __syncthreads();

        #pragma unroll 1
        for (int kt = 0; kt < 32; kt++) {
            const int cur = kt & 1, nxt = cur ^ 1;
            const bool hn = (kt + 1 < 32);
            if (hn) {
                const int k2 = kt + 1;
                const float* Ab = (k2 < 16) ? Ai : Aj;
                const int kc = (k2 & 15) * 16;
                av = *(const float4*)&Ab[(size_t)a_row * EMBED + kc + a_kb];
                const float* Bt = Bp + (size_t)(k2 * 16) * EMBED;
                PREF_B(Bt);
            }
            tile_mma(smA + cur * AS_BUF, smB + cur * BS_BUF, tig, g, wn, hacc);
            if (hn) { STORE_A(smA + nxt * AS_BUF, av); STORE_B(smB + nxt * BS_BUF); }
            __syncthreads();
        }

        // ---- epilogue 1: tanh -> tf32 -> Hs[k=d][m'] (stage-2 A layout) ----
        const float* Bf = W_final + (size_t)p * EMBED * EMBED;
        PREF_B(Bf);   // prefetch stage-2 B tile 0 (overlaps epilogue)

        #pragma unroll
        for (int ni = 0; ni < 4; ni++) {
            const int c = wn + ni * 8 + tig * 2;
            const float2 bb = *(const float2*)&b_pair[p * EMBED + c];
            const int sw = 2 * (c & 12);   // same for c and c+1 (c even, c&3 != 3)
            #pragma unroll
            for (int mi = 0; mi < 4; mi++) {
                const int r0 = mi * 16 + g, r1 = r0 + 8;
                Hs[(c    ) * ASTR + ((r0 + sw) & 63)] = f2tf(fast_tanh(hacc[mi][ni][0] + bb.x));
                Hs[(c + 1) * ASTR + ((r0 + sw) & 63)] = f2tf(fast_tanh(hacc[mi][ni][1] + bb.y));
                Hs[(c    ) * ASTR + ((r1 + sw) & 63)] = f2tf(fast_tanh(hacc[mi][ni][2] + bb.x));
                Hs[(c + 1) * ASTR + ((r1 + sw) & 63)] = f2tf(fast_tanh(hacc[mi][ni][3] + bb.y));
            }
        }
        STORE_B(smB);           // stage-2 B tile 0 -> buffer 0
        __syncthreads();

        // ---- stage 2: oacc += Hs(64x256) @ Wf_p(256x256)  (16 k-tiles) ----
        #pragma unroll 1
        for (int kt = 0; kt < 16; kt++) {
            const int cur = kt & 1, nxt = cur ^ 1;
            const bool hn = (kt + 1 < 16);
            if (hn) {
                const float* Bt = Bf + (size_t)((kt + 1) * 16) * EMBED;
                PREF_B(Bt);
            }
            tile_mma(Hs + kt * 16 * ASTR, smB + cur * BS_BUF, tig, g, wn, oacc);
            if (hn) STORE_B(smB + nxt * BS_BUF);
            __syncthreads();
        }
    }

    // ---- final epilogue: + b_final -> out ----
    #pragma unroll
    for (int ni = 0; ni < 4; ni++) {
        const int c = wn + ni * 8 + tig * 2;
        const float2 bb = *(const float2*)&b_final[c];
        #pragma unroll
        for (int mi = 0; mi < 4; mi++) {
            const int r0 = row0 + mi * 16 + g, r1 = r0 + 8;
            float2 v0 = make_float2(oacc[mi][ni][0] + bb.x, oacc[mi][ni][1] + bb.y);
            float2 v1 = make_float2(oacc[mi][ni][2] + bb.x, oacc[mi][ni][3] + bb.y);
            *(float2*)&out[(size_t)r0 * EMBED + c] = v0;
            *(float2*)&out[(size_t)r1 * EMBED + c] = v1;
        }
    }
#undef STORE_A
#undef PREF_B
#undef STORE_B
}

// ---------------- launch ----------------
extern "C" void kernel_launch(void* const* d_in, const int* in_sizes, int n_in,
                              void* d_out, int out_size) {
    const float* features = (const float*)d_in[0];
    const float* W_pair   = (const float*)d_in[1];
    const float* b_pair   = (const float*)d_in[2];
    const float* W_final  = (const float*)d_in[3];
    const float* b_final  = (const float*)d_in[4];
    const int*   NAS      = (const int*)d_in[5];
    float* out = (float*)d_out;

    static int attr_set = 0;
    if (!attr_set) {
        cudaFuncSetAttribute(fused_kernel, cudaFuncAttributeMaxDynamicSharedMemorySize,
                             SMEM_BYTES);
        attr_set = 1;
    }

    fused_kernel<<<TOKENS / BM, 256, SMEM_BYTES>>>(
        features, W_pair, b_pair, W_final, b_final, NAS, out);
}